// round 15
// baseline (speedup 1.0000x reference)
#include <cuda_runtime.h>
#include <math.h>

#define TPB 256
#define MAXK 128

// Per-batch accumulators: [b*3 + {stc,str,cnt}]. Zero-initialized at load;
// the LAST block of every run resets them to zero after reading, so graph
// replays are deterministic with no init kernel.
__device__ float g_acc[16];
// Wrap-around completion counter (returns to 0 after each full run).
__device__ unsigned g_ctr = 0;

__device__ __forceinline__ float softplusf(float z) {
    // log(1 + exp(z)), stable
    return fmaxf(z, 0.f) + log1pf(__expf(-fabsf(z)));
}

__global__ __launch_bounds__(TPB) void loss_kernel(
    const float* __restrict__ prop,     // (B, A, 6)
    const float* __restrict__ anchors,  // (A, 4) xywh
    const float* __restrict__ gt,       // (B, K, 4) xywh
    float* __restrict__ out,
    int A, int K, int B, int totalBlocks)
{
    __shared__ float4 s_g[MAXK];        // gt boxes xyxy
    __shared__ float4 s_ga4[MAXK / 4];  // gt areas, packed 4-per-float4
    __shared__ float  r0[8], r1[8], r2[8];
    __shared__ int    s_last;

    const int b = blockIdx.y;

    for (int k = threadIdx.x; k < K; k += TPB) {
        const float* g = gt + ((size_t)b * K + k) * 4;
        float gx = g[0], gy = g[1], gw = g[2], gh = g[3];
        s_g[k] = make_float4(gx, gy, gx + gw, gy + gh);
        ((float*)s_ga4)[k] = gw * gh;
    }
    __syncthreads();

    const int a = blockIdx.x * TPB + threadIdx.x;
    float stc = 0.f, strl = 0.f, cnt = 0.f;

    if (a < A) {
        float4 an = reinterpret_cast<const float4*>(anchors)[a];
        const float ax1 = an.x, ay1 = an.y;
        const float ax2 = an.x + an.z, ay2 = an.y + an.w;
        const float areaA = an.z * an.w;

        // Division-free argmax in S-form, 2x units:
        //   inter2 = (w+|w|)*h = 2*max(w,0)*h exactly (w+|w| on fma pipe,
        //   |.| free modifier). If h<0, inter2<0 and can never win the strict
        //   compare (rhs >= 0); when selected inter2>0 => w,h>0 => exact.
        //   iou_k > iou_best <=> inter2_k*S_best > inter2_best*S_k (both x2).
        //   ts = bI2 / (2*bS - bI2)  (exact scaling).
        float bI2 = 0.f, bS = 1.f;
        int   bK = 0;
#pragma unroll 8
        for (int k = 0; k < K; k++) {
            float4 g  = s_g[k];
            float  ga = ((const float*)s_ga4)[k];   // LDS.128 per 4 iters
            float w = fminf(ax2, g.z) - fmaxf(ax1, g.x);
            float h = fminf(ay2, g.w) - fmaxf(ay1, g.y);
            float inter2 = (w + fabsf(w)) * h;
            float S = areaA + ga;
            if (inter2 * bS > bI2 * S) { bI2 = inter2; bS = S; bK = k; }
        }
        const float ts = bI2 / (2.f * bS - bI2);   // target_score = max IoU

        const float* p = prop + ((size_t)b * A + a) * 6;
        float2 p01 = *reinterpret_cast<const float2*>(p);
        float2 p23 = *reinterpret_cast<const float2*>(p + 2);
        const float x = p[4];  // logit
        const float sig = 1.f / (1.f + __expf(-x));

        if (ts >= 0.5f) {
            cnt = 1.f;
            // focal with t=1: alpha * softplus(-x) * (1-p)^2
            float om = 1.f - sig;
            stc = 0.25f * softplusf(-x) * om * om;
            // elementwise IoU(pred box, matched gt box)
            float4 g = s_g[bK];
            float gab = ((const float*)s_ga4)[bK];
            float px2 = p01.x + p23.x, py2 = p01.y + p23.y;
            float ew = fmaxf(fminf(px2, g.z) - fmaxf(p01.x, g.x), 0.f);
            float eh = fmaxf(fminf(py2, g.w) - fmaxf(p01.y, g.y), 0.f);
            float ei = ew * eh;
            float eiou = ei / ((p23.x * p23.y + gab) - ei);
            strl = -__logf(eiou + 0.01f);
        } else if (ts < 0.4f) {
            // focal with t=0: (1-alpha) * softplus(x) * p^2
            stc = 0.75f * softplusf(x) * sig * sig;
        }
    }

    // block reduction of (stc, strl, cnt)
    const unsigned m = 0xFFFFFFFFu;
#pragma unroll
    for (int o = 16; o; o >>= 1) {
        stc  += __shfl_down_sync(m, stc,  o);
        strl += __shfl_down_sync(m, strl, o);
        cnt  += __shfl_down_sync(m, cnt,  o);
    }
    const int wid = threadIdx.x >> 5, lane = threadIdx.x & 31;
    if (lane == 0) { r0[wid] = stc; r1[wid] = strl; r2[wid] = cnt; }
    __syncthreads();

    if (threadIdx.x == 0) {
        float t0 = 0.f, t1 = 0.f, t2 = 0.f;
#pragma unroll
        for (int i = 0; i < TPB / 32; i++) { t0 += r0[i]; t1 += r1[i]; t2 += r2[i]; }
        // accumulate straight into the 12-float global accumulator
        atomicAdd(&g_acc[b * 3 + 0], t0);
        atomicAdd(&g_acc[b * 3 + 1], t1);
        atomicAdd(&g_acc[b * 3 + 2], t2);
        __threadfence();
        unsigned old = atomicInc(&g_ctr, (unsigned)(totalBlocks - 1));
        s_last = (old == (unsigned)(totalBlocks - 1)) ? 1 : 0;
    }
    __syncthreads();

    // last block: finalize (12 floats) and reset accumulators for next replay
    if (s_last && threadIdx.x == 0) {
        float t = 0.f;
        for (int bb = 0; bb < B; bb++) {
            float c = g_acc[bb * 3 + 2];
            float safe = (c > 0.f) ? c : 1.f;
            t += g_acc[bb * 3 + 0] / safe;                 // stc (undivided if no pos)
            if (c > 0.f) t += g_acc[bb * 3 + 1] / safe;    // str (0 if no pos)
        }
        out[0] = t / (float)B;
        for (int i = 0; i < 16; i++) g_acc[i] = 0.f;       // reset for determinism
    }
}

extern "C" void kernel_launch(void* const* d_in, const int* in_sizes, int n_in,
                              void* d_out, int out_size) {
    const float* prop    = (const float*)d_in[0];  // ss_proposal (B,A,6)
    const float* anchors = (const float*)d_in[1];  // anchors (A,4)
    const float* gt      = (const float*)d_in[2];  // ground_truth (B,K,4)

    const int A = in_sizes[1] / 4;
    const int B = in_sizes[0] / (A * 6);
    const int K = in_sizes[2] / (B * 4);

    const int gx = (A + TPB - 1) / TPB;     // 469 for A=120000
    dim3 grid(gx, B);
    const int total = gx * B;

    loss_kernel<<<grid, TPB>>>(prop, anchors, gt, (float*)d_out, A, K, B, total);
}

// round 16
// speedup vs baseline: 1.0849x; 1.0849x over previous
#include <cuda_runtime.h>
#include <math.h>

#define TPB 256
#define MAXK 128

// Per-batch accumulators: [b*3 + {stc,str,cnt}]. Zero-initialized at load;
// the LAST block of every run resets them to zero after reading, so graph
// replays are deterministic with no init kernel.
__device__ float g_acc[16];
// Wrap-around completion counter (returns to 0 after each full run).
__device__ unsigned g_ctr = 0;

__device__ __forceinline__ float softplusf(float z) {
    // log(1 + exp(z)), stable
    return fmaxf(z, 0.f) + log1pf(__expf(-fabsf(z)));
}

template<int KFIX>
__global__ __launch_bounds__(TPB, 6) void loss_kernel(
    const float* __restrict__ prop,     // (B, A, 6)
    const float* __restrict__ anchors,  // (A, 4) xywh
    const float* __restrict__ gt,       // (B, K, 4) xywh
    float* __restrict__ out,
    int A, int Krt, int B, int totalBlocks)
{
    const int K = (KFIX > 0) ? KFIX : Krt;
    __shared__ float4 s_g[MAXK];        // gt boxes xyxy
    __shared__ float4 s_ga4[MAXK / 4];  // gt areas, packed 4-per-float4
    __shared__ float  r0[8], r1[8], r2[8];
    __shared__ int    s_last;

    const int b = blockIdx.y;

    for (int k = threadIdx.x; k < K; k += TPB) {
        const float* g = gt + ((size_t)b * K + k) * 4;
        float gx = g[0], gy = g[1], gw = g[2], gh = g[3];
        s_g[k] = make_float4(gx, gy, gx + gw, gy + gh);
        ((float*)s_ga4)[k] = gw * gh;
    }
    __syncthreads();

    const int a = blockIdx.x * TPB + threadIdx.x;
    float stc = 0.f, strl = 0.f, cnt = 0.f;

    if (a < A) {
        float4 an = reinterpret_cast<const float4*>(anchors)[a];
        const float ax1 = an.x, ay1 = an.y;
        const float ax2 = an.x + an.z, ay2 = an.y + an.w;
        const float areaA = an.z * an.w;

        // Division-free argmax in S-form, 2x units:
        //   inter2 = (w+|w|)*h = 2*max(w,0)*h exactly (w+|w| on fma pipe,
        //   |.| free modifier). If h<0, inter2<0 and can never win the strict
        //   compare (rhs >= 0); when selected inter2>0 => w,h>0 => exact.
        //   iou_k > iou_best <=> inter2_k*S_best > inter2_best*S_k (both x2).
        //   ts = bI2 / (2*bS - bI2)  (exact scaling).
        float bI2 = 0.f, bS = 1.f;
        int   bK = 0;
        if (KFIX > 0) {
#pragma unroll
            for (int k = 0; k < KFIX; k++) {
                float4 g  = s_g[k];
                float  ga = ((const float*)s_ga4)[k];   // LDS.128 per 4 iters
                float w = fminf(ax2, g.z) - fmaxf(ax1, g.x);
                float h = fminf(ay2, g.w) - fmaxf(ay1, g.y);
                float inter2 = (w + fabsf(w)) * h;
                float S = areaA + ga;
                if (inter2 * bS > bI2 * S) { bI2 = inter2; bS = S; bK = k; }
            }
        } else {
#pragma unroll 8
            for (int k = 0; k < K; k++) {
                float4 g  = s_g[k];
                float  ga = ((const float*)s_ga4)[k];
                float w = fminf(ax2, g.z) - fmaxf(ax1, g.x);
                float h = fminf(ay2, g.w) - fmaxf(ay1, g.y);
                float inter2 = (w + fabsf(w)) * h;
                float S = areaA + ga;
                if (inter2 * bS > bI2 * S) { bI2 = inter2; bS = S; bK = k; }
            }
        }
        const float ts = bI2 / (2.f * bS - bI2);   // target_score = max IoU

        const float* p = prop + ((size_t)b * A + a) * 6;
        float2 p01 = *reinterpret_cast<const float2*>(p);
        float2 p23 = *reinterpret_cast<const float2*>(p + 2);
        const float x = p[4];  // logit
        const float sig = 1.f / (1.f + __expf(-x));

        if (ts >= 0.5f) {
            cnt = 1.f;
            // focal with t=1: alpha * softplus(-x) * (1-p)^2
            float om = 1.f - sig;
            stc = 0.25f * softplusf(-x) * om * om;
            // elementwise IoU(pred box, matched gt box)
            float4 g = s_g[bK];
            float gab = ((const float*)s_ga4)[bK];
            float px2 = p01.x + p23.x, py2 = p01.y + p23.y;
            float ew = fmaxf(fminf(px2, g.z) - fmaxf(p01.x, g.x), 0.f);
            float eh = fmaxf(fminf(py2, g.w) - fmaxf(p01.y, g.y), 0.f);
            float ei = ew * eh;
            float eiou = ei / ((p23.x * p23.y + gab) - ei);
            strl = -__logf(eiou + 0.01f);
        } else if (ts < 0.4f) {
            // focal with t=0: (1-alpha) * softplus(x) * p^2
            stc = 0.75f * softplusf(x) * sig * sig;
        }
    }

    // block reduction of (stc, strl, cnt)
    const unsigned m = 0xFFFFFFFFu;
#pragma unroll
    for (int o = 16; o; o >>= 1) {
        stc  += __shfl_down_sync(m, stc,  o);
        strl += __shfl_down_sync(m, strl, o);
        cnt  += __shfl_down_sync(m, cnt,  o);
    }
    const int wid = threadIdx.x >> 5, lane = threadIdx.x & 31;
    if (lane == 0) { r0[wid] = stc; r1[wid] = strl; r2[wid] = cnt; }
    __syncthreads();

    if (threadIdx.x == 0) {
        float t0 = 0.f, t1 = 0.f, t2 = 0.f;
#pragma unroll
        for (int i = 0; i < TPB / 32; i++) { t0 += r0[i]; t1 += r1[i]; t2 += r2[i]; }
        // accumulate straight into the 12-float global accumulator
        atomicAdd(&g_acc[b * 3 + 0], t0);
        atomicAdd(&g_acc[b * 3 + 1], t1);
        atomicAdd(&g_acc[b * 3 + 2], t2);
        __threadfence();
        unsigned old = atomicInc(&g_ctr, (unsigned)(totalBlocks - 1));
        s_last = (old == (unsigned)(totalBlocks - 1)) ? 1 : 0;
    }
    __syncthreads();

    // last block: finalize (12 floats) and reset accumulators for next replay
    if (s_last && threadIdx.x == 0) {
        float t = 0.f;
        for (int bb = 0; bb < B; bb++) {
            float c = g_acc[bb * 3 + 2];
            float safe = (c > 0.f) ? c : 1.f;
            t += g_acc[bb * 3 + 0] / safe;                 // stc (undivided if no pos)
            if (c > 0.f) t += g_acc[bb * 3 + 1] / safe;    // str (0 if no pos)
        }
        out[0] = t / (float)B;
        for (int i = 0; i < 16; i++) g_acc[i] = 0.f;       // reset for determinism
    }
}

extern "C" void kernel_launch(void* const* d_in, const int* in_sizes, int n_in,
                              void* d_out, int out_size) {
    const float* prop    = (const float*)d_in[0];  // ss_proposal (B,A,6)
    const float* anchors = (const float*)d_in[1];  // anchors (A,4)
    const float* gt      = (const float*)d_in[2];  // ground_truth (B,K,4)

    const int A = in_sizes[1] / 4;
    const int B = in_sizes[0] / (A * 6);
    const int K = in_sizes[2] / (B * 4);

    const int gx = (A + TPB - 1) / TPB;     // 469 for A=120000
    dim3 grid(gx, B);
    const int total = gx * B;

    if (K == 64)
        loss_kernel<64><<<grid, TPB>>>(prop, anchors, gt, (float*)d_out, A, K, B, total);
    else
        loss_kernel<0><<<grid, TPB>>>(prop, anchors, gt, (float*)d_out, A, K, B, total);
}

// round 17
// speedup vs baseline: 1.0862x; 1.0012x over previous
#include <cuda_runtime.h>
#include <math.h>

#define TPB 256
#define MAXK 128

// Per-batch accumulators: [b*3 + {stc,str,cnt}]. Zero-initialized at load;
// the LAST block of every run resets them to zero after reading, so graph
// replays are deterministic with no init kernel.
__device__ float g_acc[16];
// Wrap-around completion counter (returns to 0 after each full run).
__device__ unsigned g_ctr = 0;

__device__ __forceinline__ float softplusf(float z) {
    // log(1 + exp(z)), stable
    return fmaxf(z, 0.f) + log1pf(__expf(-fabsf(z)));
}

template<int KFIX>
__global__ __launch_bounds__(TPB, 5) void loss_kernel(
    const float* __restrict__ prop,     // (B, A, 6)
    const float* __restrict__ anchors,  // (A, 4) xywh
    const float* __restrict__ gt,       // (B, K, 4) xywh
    float* __restrict__ out,
    int A, int Krt, int B, int totalBlocks)
{
    const int K = (KFIX > 0) ? KFIX : Krt;
    __shared__ float4 s_g[MAXK];        // gt boxes xyxy
    __shared__ float4 s_ga4[MAXK / 4];  // gt areas, packed 4-per-float4
    __shared__ float  r0[8], r1[8], r2[8];
    __shared__ int    s_last;

    const int b = blockIdx.y;

    for (int k = threadIdx.x; k < K; k += TPB) {
        const float* g = gt + ((size_t)b * K + k) * 4;
        float gx = g[0], gy = g[1], gw = g[2], gh = g[3];
        s_g[k] = make_float4(gx, gy, gx + gw, gy + gh);
        ((float*)s_ga4)[k] = gw * gh;
    }
    __syncthreads();

    const int a = blockIdx.x * TPB + threadIdx.x;
    const int c = min(a, A - 1);        // clamped index; masked via (a < A)

    // Prefetch anchor + proposal BEFORE the K-loop so the ~600-cyc LDG
    // latency is hidden behind 64 iterations of compute.
    const float4 an  = reinterpret_cast<const float4*>(anchors)[c];
    const float* p   = prop + ((size_t)b * A + c) * 6;
    const float2 p01 = *reinterpret_cast<const float2*>(p);
    const float2 p23 = *reinterpret_cast<const float2*>(p + 2);
    const float  x   = p[4];            // logit

    const float ax1 = an.x, ay1 = an.y;
    const float ax2 = an.x + an.z, ay2 = an.y + an.w;
    const float areaA = an.z * an.w;

    // Division-free argmax in S-form, 2x units:
    //   inter2 = (w+|w|)*h = 2*max(w,0)*h exactly (w+|w| on fma pipe,
    //   |.| free modifier). If h<0, inter2<0 and can never win the strict
    //   compare (rhs >= 0); when selected inter2>0 => w,h>0 => exact.
    //   iou_k > iou_best <=> inter2_k*S_best > inter2_best*S_k (both x2).
    //   ts = bI2 / (2*bS - bI2)  (exact scaling).
    float bI2 = 0.f, bS = 1.f;
    int   bK = 0;
    if (KFIX > 0) {
#pragma unroll
        for (int k = 0; k < KFIX; k++) {
            float4 g  = s_g[k];
            float  ga = ((const float*)s_ga4)[k];   // LDS.128 per 4 iters
            float w = fminf(ax2, g.z) - fmaxf(ax1, g.x);
            float h = fminf(ay2, g.w) - fmaxf(ay1, g.y);
            float inter2 = (w + fabsf(w)) * h;
            float S = areaA + ga;
            if (inter2 * bS > bI2 * S) { bI2 = inter2; bS = S; bK = k; }
        }
    } else {
#pragma unroll 8
        for (int k = 0; k < K; k++) {
            float4 g  = s_g[k];
            float  ga = ((const float*)s_ga4)[k];
            float w = fminf(ax2, g.z) - fmaxf(ax1, g.x);
            float h = fminf(ay2, g.w) - fmaxf(ay1, g.y);
            float inter2 = (w + fabsf(w)) * h;
            float S = areaA + ga;
            if (inter2 * bS > bI2 * S) { bI2 = inter2; bS = S; bK = k; }
        }
    }

    float stc = 0.f, strl = 0.f, cnt = 0.f;

    if (a < A) {
        const float ts = bI2 / (2.f * bS - bI2);   // target_score = max IoU
        const float sig = 1.f / (1.f + __expf(-x));

        if (ts >= 0.5f) {
            cnt = 1.f;
            // focal with t=1: alpha * softplus(-x) * (1-p)^2
            float om = 1.f - sig;
            stc = 0.25f * softplusf(-x) * om * om;
            // elementwise IoU(pred box, matched gt box)
            float4 g = s_g[bK];
            float gab = ((const float*)s_ga4)[bK];
            float px2 = p01.x + p23.x, py2 = p01.y + p23.y;
            float ew = fmaxf(fminf(px2, g.z) - fmaxf(p01.x, g.x), 0.f);
            float eh = fmaxf(fminf(py2, g.w) - fmaxf(p01.y, g.y), 0.f);
            float ei = ew * eh;
            float eiou = ei / ((p23.x * p23.y + gab) - ei);
            strl = -__logf(eiou + 0.01f);
        } else if (ts < 0.4f) {
            // focal with t=0: (1-alpha) * softplus(x) * p^2
            stc = 0.75f * softplusf(x) * sig * sig;
        }
    }

    // block reduction of (stc, strl, cnt)
    const unsigned m = 0xFFFFFFFFu;
#pragma unroll
    for (int o = 16; o; o >>= 1) {
        stc  += __shfl_down_sync(m, stc,  o);
        strl += __shfl_down_sync(m, strl, o);
        cnt  += __shfl_down_sync(m, cnt,  o);
    }
    const int wid = threadIdx.x >> 5, lane = threadIdx.x & 31;
    if (lane == 0) { r0[wid] = stc; r1[wid] = strl; r2[wid] = cnt; }
    __syncthreads();

    if (threadIdx.x == 0) {
        float t0 = 0.f, t1 = 0.f, t2 = 0.f;
#pragma unroll
        for (int i = 0; i < TPB / 32; i++) { t0 += r0[i]; t1 += r1[i]; t2 += r2[i]; }
        // accumulate straight into the 12-float global accumulator
        atomicAdd(&g_acc[b * 3 + 0], t0);
        atomicAdd(&g_acc[b * 3 + 1], t1);
        atomicAdd(&g_acc[b * 3 + 2], t2);
        __threadfence();
        unsigned old = atomicInc(&g_ctr, (unsigned)(totalBlocks - 1));
        s_last = (old == (unsigned)(totalBlocks - 1)) ? 1 : 0;
    }
    __syncthreads();

    // last block: finalize (12 floats) and reset accumulators for next replay
    if (s_last && threadIdx.x == 0) {
        float t = 0.f;
        for (int bb = 0; bb < B; bb++) {
            float cc = g_acc[bb * 3 + 2];
            float safe = (cc > 0.f) ? cc : 1.f;
            t += g_acc[bb * 3 + 0] / safe;                 // stc (undivided if no pos)
            if (cc > 0.f) t += g_acc[bb * 3 + 1] / safe;   // str (0 if no pos)
        }
        out[0] = t / (float)B;
        for (int i = 0; i < 16; i++) g_acc[i] = 0.f;       // reset for determinism
    }
}

extern "C" void kernel_launch(void* const* d_in, const int* in_sizes, int n_in,
                              void* d_out, int out_size) {
    const float* prop    = (const float*)d_in[0];  // ss_proposal (B,A,6)
    const float* anchors = (const float*)d_in[1];  // anchors (A,4)
    const float* gt      = (const float*)d_in[2];  // ground_truth (B,K,4)

    const int A = in_sizes[1] / 4;
    const int B = in_sizes[0] / (A * 6);
    const int K = in_sizes[2] / (B * 4);

    const int gx = (A + TPB - 1) / TPB;     // 469 for A=120000
    dim3 grid(gx, B);
    const int total = gx * B;

    if (K == 64)
        loss_kernel<64><<<grid, TPB>>>(prop, anchors, gt, (float*)d_out, A, K, B, total);
    else
        loss_kernel<0><<<grid, TPB>>>(prop, anchors, gt, (float*)d_out, A, K, B, total);
}